// round 1
// baseline (speedup 1.0000x reference)
#include <cuda_runtime.h>

// ---------------------------------------------------------------------------
// Problem constants
// ---------------------------------------------------------------------------
#define B_    64
#define T_    12
#define HOR_  12
#define NN_   1024
#define HH_   64

// Scratch layout (offsets in floats inside one big __device__ buffer)
constexpr int OFF_A    = 0;                         // [1024,1024]
constexpr int OFF_X    = OFF_A    + 1024 * 1024;    // [1024, 768]  (n, t*64+b)
constexpr int OFF_AX   = OFF_X    + 1024 * 768;
constexpr int OFF_A2X  = OFF_AX   + 1024 * 768;
constexpr int OFF_Y    = OFF_A2X  + 1024 * 768;
constexpr int OFF_AY   = OFF_Y    + 1024 * 768;
constexpr int OFF_A2Y  = OFF_AY   + 1024 * 768;
constexpr int OFF_H    = OFF_A2Y  + 1024 * 768;     // [1024, 4096] == [65536,64]
constexpr int OFF_AH   = OFF_H    + 4194304;
constexpr int OFF_A2H  = OFF_AH   + 4194304;
constexpr int OFF_ZH   = OFF_A2H  + 4194304;
constexpr int OFF_AZH  = OFF_ZH   + 4194304;
constexpr int OFF_A2ZH = OFF_AZH  + 4194304;
constexpr int OFF_R    = OFF_A2ZH + 4194304;
constexpr int OFF_GO   = OFF_R    + 4194304;        // [65536]
constexpr int OFF_AGO  = OFF_GO   + 65536;
constexpr int OFF_A2GO = OFF_AGO  + 65536;
constexpr int SCRATCH_TOTAL = OFF_A2GO + 65536;     // ~141 MB

__device__ float g_scratch[SCRATCH_TOTAL];

// ---------------------------------------------------------------------------
// A = softmax(relu(E @ E^T), axis=-1),  E: [1024, 8]
// One block per row.
// ---------------------------------------------------------------------------
__global__ void __launch_bounds__(256) build_A(const float* __restrict__ emb) {
    __shared__ float Es[1024 * 8];
    __shared__ float red[256];
    const int tid = threadIdx.x;
    for (int i = tid; i < 1024 * 8; i += 256) Es[i] = emb[i];
    __syncthreads();

    const int r = blockIdx.x;
    float er[8];
#pragma unroll
    for (int j = 0; j < 8; j++) er[j] = Es[r * 8 + j];

    float v[4];
    float mx = -1e30f;
#pragma unroll
    for (int i = 0; i < 4; i++) {
        const int c = tid + i * 256;
        float s = 0.f;
#pragma unroll
        for (int j = 0; j < 8; j++) s += er[j] * Es[c * 8 + j];
        s = fmaxf(s, 0.f);
        v[i] = s;
        mx = fmaxf(mx, s);
    }
    red[tid] = mx;
    __syncthreads();
    for (int o = 128; o > 0; o >>= 1) {
        if (tid < o) red[tid] = fmaxf(red[tid], red[tid + o]);
        __syncthreads();
    }
    mx = red[0];
    __syncthreads();

    float sum = 0.f;
#pragma unroll
    for (int i = 0; i < 4; i++) {
        v[i] = expf(v[i] - mx);
        sum += v[i];
    }
    red[tid] = sum;
    __syncthreads();
    for (int o = 128; o > 0; o >>= 1) {
        if (tid < o) red[tid] += red[tid + o];
        __syncthreads();
    }
    const float inv = 1.f / red[0];
#pragma unroll
    for (int i = 0; i < 4; i++)
        g_scratch[OFF_A + r * 1024 + tid + i * 256] = v[i] * inv;
}

// ---------------------------------------------------------------------------
// Node-major transposes of x and y_cov:  X[n, t*64+b] = x[b,t,n,0]
// ---------------------------------------------------------------------------
__global__ void __launch_bounds__(256) make_XY(const float* __restrict__ x,
                                               const float* __restrict__ y) {
    const int idx = blockIdx.x * 256 + threadIdx.x;   // 1024*768
    if (idx >= 1024 * 768) return;
    const int n = idx / 768, col = idx % 768;
    const int t = col >> 6, b = col & 63;
    g_scratch[OFF_X + idx] = x[(b * T_ + t) * NN_ + n];
    g_scratch[OFF_Y + idx] = y[(b * HOR_ + t) * NN_ + n];
}

__global__ void __launch_bounds__(256) zero_state() {
    const int i = blockIdx.x * 256 + threadIdx.x;
    if (i < 4194304) g_scratch[OFF_H + i] = 0.f;
    if (i < 65536) {
        g_scratch[OFF_GO + i]   = 0.f;
        g_scratch[OFF_AGO + i]  = 0.f;
        g_scratch[OFF_A2GO + i] = 0.f;
    }
}

// ---------------------------------------------------------------------------
// Tiled fp32 GEMM: C[M,Nn] = A[M,Kd] @ B[Kd,Nn]  (row-major, all scratch)
//   mode 0: C = A@B
//   mode 1: C = 2*A@B - D        (Chebyshev recurrence)
// Requires M%128==0, Nn%128==0, Kd%16==0. BM=BN=128, BK=16, 256 thr, 8x8 micro.
// ---------------------------------------------------------------------------
__global__ void __launch_bounds__(256) sgemm128(int offA, int offB, int offD,
                                                int offC, int Nn, int Kd,
                                                int mode) {
    __shared__ float As[16][128];
    __shared__ float Bs[16][128];
    const float* Am = g_scratch + offA;
    const float* Bm = g_scratch + offB;
    float* Cm = g_scratch + offC;

    const int tid = threadIdx.x;
    const int row0 = blockIdx.y * 128, col0 = blockIdx.x * 128;
    const int tx = tid & 15, ty = tid >> 4;

    float acc[8][8];
#pragma unroll
    for (int i = 0; i < 8; i++)
#pragma unroll
        for (int j = 0; j < 8; j++) acc[i][j] = 0.f;

    const int ar = tid >> 2;
    const int ac = (tid & 3) << 2;
    const int br = tid >> 5;
    const int bc = (tid & 31) << 2;
    const float* Ap = Am + (row0 + ar) * Kd + ac;
    const float* Bp = Bm + br * Nn + col0 + bc;

    for (int k0 = 0; k0 < Kd; k0 += 16) {
        const float4 a0 = *(const float4*)(Ap);
        const float4 a1 = *(const float4*)(Ap + (Kd << 6));
        const float4 b0 = *(const float4*)(Bp);
        const float4 b1 = *(const float4*)(Bp + (Nn << 3));
        __syncthreads();
        As[ac + 0][ar] = a0.x; As[ac + 1][ar] = a0.y;
        As[ac + 2][ar] = a0.z; As[ac + 3][ar] = a0.w;
        As[ac + 0][ar + 64] = a1.x; As[ac + 1][ar + 64] = a1.y;
        As[ac + 2][ar + 64] = a1.z; As[ac + 3][ar + 64] = a1.w;
        *(float4*)(&Bs[br][bc])     = b0;
        *(float4*)(&Bs[br + 8][bc]) = b1;
        __syncthreads();
#pragma unroll
        for (int k = 0; k < 16; k++) {
            const float4 xa = *(const float4*)&As[k][ty << 2];
            const float4 xb = *(const float4*)&As[k][64 + (ty << 2)];
            const float4 ya = *(const float4*)&Bs[k][tx << 2];
            const float4 yb = *(const float4*)&Bs[k][64 + (tx << 2)];
            const float ra[8] = {xa.x, xa.y, xa.z, xa.w, xb.x, xb.y, xb.z, xb.w};
            const float rb[8] = {ya.x, ya.y, ya.z, ya.w, yb.x, yb.y, yb.z, yb.w};
#pragma unroll
            for (int i = 0; i < 8; i++)
#pragma unroll
                for (int j = 0; j < 8; j++)
                    acc[i][j] = fmaf(ra[i], rb[j], acc[i][j]);
        }
        Ap += 16;
        Bp += Nn << 4;
    }

#pragma unroll
    for (int rr = 0; rr < 2; rr++)
#pragma unroll
        for (int ii = 0; ii < 4; ii++) {
            const int gr = row0 + rr * 64 + (ty << 2) + ii;
            const int ai = rr * 4 + ii;
#pragma unroll
            for (int cc = 0; cc < 2; cc++) {
                const int gc = col0 + cc * 64 + (tx << 2);
                float4 v = make_float4(acc[ai][cc * 4 + 0], acc[ai][cc * 4 + 1],
                                       acc[ai][cc * 4 + 2], acc[ai][cc * 4 + 3]);
                if (mode == 1) {
                    const float4 d = *(const float4*)(g_scratch + offD + gr * Nn + gc);
                    v.x = 2.f * v.x - d.x; v.y = 2.f * v.y - d.y;
                    v.z = 2.f * v.z - d.z; v.w = 2.f * v.w - d.w;
                }
                *(float4*)(Cm + gr * Nn + gc) = v;
            }
        }
}

// ---------------------------------------------------------------------------
// Feature gather shared by the fused GCN GEMMs.
// Row m = n*64+b. K-order: k-major, within k: NXC scalar channels then 64 h.
// ---------------------------------------------------------------------------
template <int NXC>
__device__ __forceinline__ float gcn_feat(
    int m, int kk, const float* h0, const float* h1, const float* h2,
    const float* x0, const float* x1, const float* x2,
    const float* y0, const float* y1, const float* y2,
    int str0, int off0, int str1, int off1) {
    constexpr int CPK = NXC + 64;
    const int kseg = (kk >= 2 * CPK) ? 2 : ((kk >= CPK) ? 1 : 0);
    const int c = kk - kseg * CPK;
    if (c >= NXC) {
        const float* h = (kseg == 0) ? h0 : ((kseg == 1) ? h1 : h2);
        return h[m * 64 + (c - NXC)];
    } else if (NXC == 2 && c == 1) {
        const float* p = (kseg == 0) ? y0 : ((kseg == 1) ? y1 : y2);
        return p[(m >> 6) * str1 + off1 + (m & 63)];
    } else {
        const float* p = (kseg == 0) ? x0 : ((kseg == 1) ? x1 : x2);
        return p[(m >> 6) * str0 + off0 + (m & 63)];
    }
}

// ---------------------------------------------------------------------------
// Fused gate GCN:  ZR = sigmoid(F @ W + b),  F gathered [65536, KTOT],
// then ZH = z * H, Rbuf = r.   NOUT = 128.  BM=128, BK=16.
// ---------------------------------------------------------------------------
template <int NXC>
__global__ void __launch_bounds__(256) gcn_gate(
    int oh0, int oh1, int oh2, int ox0, int ox1, int ox2,
    int oy0, int oy1, int oy2, int str0, int off0, int str1, int off1,
    const float* __restrict__ W, const float* __restrict__ bias,
    int oHold, int oZH, int oR) {
    constexpr int CPK = NXC + 64;
    constexpr int KTOT = 3 * CPK;
    __shared__ float As[16][128];
    __shared__ float Bs[16][128];

    const float* h0 = g_scratch + oh0;
    const float* h1 = g_scratch + oh1;
    const float* h2 = g_scratch + oh2;
    const float* x0 = g_scratch + ox0;
    const float* x1 = g_scratch + ox1;
    const float* x2 = g_scratch + ox2;
    const float* y0 = g_scratch + oy0;
    const float* y1 = g_scratch + oy1;
    const float* y2 = g_scratch + oy2;

    const int tid = threadIdx.x;
    const int row0 = blockIdx.x * 128;
    const int tx = tid & 15, ty = tid >> 4;
    const int am = tid >> 1;
    const int ak0 = (tid & 1) * 8;

    float acc[8][8];
#pragma unroll
    for (int i = 0; i < 8; i++)
#pragma unroll
        for (int j = 0; j < 8; j++) acc[i][j] = 0.f;

    for (int k0 = 0; k0 < KTOT; k0 += 16) {
        float av[8], wv[8];
#pragma unroll
        for (int i = 0; i < 8; i++) {
            const int kk = k0 + ak0 + i;
            av[i] = (kk < KTOT)
                        ? gcn_feat<NXC>(row0 + am, kk, h0, h1, h2, x0, x1, x2,
                                        y0, y1, y2, str0, off0, str1, off1)
                        : 0.f;
        }
#pragma unroll
        for (int i = 0; i < 8; i++) {
            const int kl = (tid >> 7) + i * 2;
            const int kk = k0 + kl;
            wv[i] = (kk < KTOT) ? W[kk * 128 + (tid & 127)] : 0.f;
        }
        __syncthreads();
#pragma unroll
        for (int i = 0; i < 8; i++) As[ak0 + i][am] = av[i];
#pragma unroll
        for (int i = 0; i < 8; i++) Bs[(tid >> 7) + i * 2][tid & 127] = wv[i];
        __syncthreads();
#pragma unroll
        for (int k = 0; k < 16; k++) {
            const float4 xa = *(const float4*)&As[k][ty << 2];
            const float4 xb = *(const float4*)&As[k][64 + (ty << 2)];
            const float4 ya = *(const float4*)&Bs[k][tx << 2];
            const float4 yb = *(const float4*)&Bs[k][64 + (tx << 2)];
            const float ra[8] = {xa.x, xa.y, xa.z, xa.w, xb.x, xb.y, xb.z, xb.w};
            const float rb[8] = {ya.x, ya.y, ya.z, ya.w, yb.x, yb.y, yb.z, yb.w};
#pragma unroll
            for (int i = 0; i < 8; i++)
#pragma unroll
                for (int j = 0; j < 8; j++)
                    acc[i][j] = fmaf(ra[i], rb[j], acc[i][j]);
        }
    }

    const float* Hold = g_scratch + oHold;
    float* ZH = g_scratch + oZH;
    float* Rb = g_scratch + oR;
#pragma unroll
    for (int rr = 0; rr < 2; rr++)
#pragma unroll
        for (int ii = 0; ii < 4; ii++) {
            const int m = row0 + rr * 64 + (ty << 2) + ii;
            const int ai = rr * 4 + ii;
#pragma unroll
            for (int j = 0; j < 4; j++) {
                const int c = (tx << 2) + j;
                const float zv = 1.f / (1.f + expf(-(acc[ai][j] + bias[c])));
                ZH[m * 64 + c] = zv * Hold[m * 64 + c];
                const float rv = 1.f / (1.f + expf(-(acc[ai][4 + j] + bias[64 + c])));
                Rb[m * 64 + c] = rv;
            }
        }
}

// ---------------------------------------------------------------------------
// Fused update GCN: hc = tanh(F @ W + b), H = r*H + (1-r)*hc.  NOUT = 64.
// ---------------------------------------------------------------------------
template <int NXC>
__global__ void __launch_bounds__(256) gcn_upd(
    int oh0, int oh1, int oh2, int ox0, int ox1, int ox2,
    int oy0, int oy1, int oy2, int str0, int off0, int str1, int off1,
    const float* __restrict__ W, const float* __restrict__ bias,
    int oH, int oR) {
    constexpr int CPK = NXC + 64;
    constexpr int KTOT = 3 * CPK;
    __shared__ float As[16][128];
    __shared__ float Bs[16][64];

    const float* h0 = g_scratch + oh0;
    const float* h1 = g_scratch + oh1;
    const float* h2 = g_scratch + oh2;
    const float* x0 = g_scratch + ox0;
    const float* x1 = g_scratch + ox1;
    const float* x2 = g_scratch + ox2;
    const float* y0 = g_scratch + oy0;
    const float* y1 = g_scratch + oy1;
    const float* y2 = g_scratch + oy2;

    const int tid = threadIdx.x;
    const int row0 = blockIdx.x * 128;
    const int tx = tid & 15, ty = tid >> 4;
    const int am = tid >> 1;
    const int ak0 = (tid & 1) * 8;

    float acc[8][4];
#pragma unroll
    for (int i = 0; i < 8; i++)
#pragma unroll
        for (int j = 0; j < 4; j++) acc[i][j] = 0.f;

    for (int k0 = 0; k0 < KTOT; k0 += 16) {
        float av[8], wv[4];
#pragma unroll
        for (int i = 0; i < 8; i++) {
            const int kk = k0 + ak0 + i;
            av[i] = (kk < KTOT)
                        ? gcn_feat<NXC>(row0 + am, kk, h0, h1, h2, x0, x1, x2,
                                        y0, y1, y2, str0, off0, str1, off1)
                        : 0.f;
        }
#pragma unroll
        for (int i = 0; i < 4; i++) {
            const int kl = (tid >> 6) + (i << 2);
            const int kk = k0 + kl;
            wv[i] = (kk < KTOT) ? W[kk * 64 + (tid & 63)] : 0.f;
        }
        __syncthreads();
#pragma unroll
        for (int i = 0; i < 8; i++) As[ak0 + i][am] = av[i];
#pragma unroll
        for (int i = 0; i < 4; i++) Bs[(tid >> 6) + (i << 2)][tid & 63] = wv[i];
        __syncthreads();
#pragma unroll
        for (int k = 0; k < 16; k++) {
            const float4 xa = *(const float4*)&As[k][ty << 2];
            const float4 xb = *(const float4*)&As[k][64 + (ty << 2)];
            const float4 yy = *(const float4*)&Bs[k][tx << 2];
            const float ra[8] = {xa.x, xa.y, xa.z, xa.w, xb.x, xb.y, xb.z, xb.w};
            const float rb[4] = {yy.x, yy.y, yy.z, yy.w};
#pragma unroll
            for (int i = 0; i < 8; i++)
#pragma unroll
                for (int j = 0; j < 4; j++)
                    acc[i][j] = fmaf(ra[i], rb[j], acc[i][j]);
        }
    }

    float* H = g_scratch + oH;
    const float* Rb = g_scratch + oR;
#pragma unroll
    for (int rr = 0; rr < 2; rr++)
#pragma unroll
        for (int ii = 0; ii < 4; ii++) {
            const int m = row0 + rr * 64 + (ty << 2) + ii;
            const int ai = rr * 4 + ii;
#pragma unroll
            for (int j = 0; j < 4; j++) {
                const int c = (tx << 2) + j;
                const float hc = tanhf(acc[ai][j] + bias[c]);
                const float rv = Rb[m * 64 + c];
                const float ho = H[m * 64 + c];
                H[m * 64 + c] = rv * ho + (1.f - rv) * hc;
            }
        }
}

// ---------------------------------------------------------------------------
// Decoder projection: go = H @ pW + pb; writes GO feedback + output slice t.
// Warp per row (8 rows / 256-thread block).
// ---------------------------------------------------------------------------
__global__ void __launch_bounds__(256) proj_kernel(const float* __restrict__ pW,
                                                   const float* __restrict__ pb,
                                                   int t, float* __restrict__ out) {
    const int row = blockIdx.x * 8 + (threadIdx.x >> 5);
    const int lane = threadIdx.x & 31;
    const float* Hp = g_scratch + OFF_H;
    float s = Hp[row * 64 + lane] * pW[lane] + Hp[row * 64 + 32 + lane] * pW[32 + lane];
#pragma unroll
    for (int o = 16; o > 0; o >>= 1) s += __shfl_xor_sync(0xffffffffu, s, o);
    if (lane == 0) {
        const float go = s + pb[0];
        g_scratch[OFF_GO + row] = go;
        const int n = row >> 6, b = row & 63;
        out[(b * HOR_ + t) * NN_ + n] = go;
    }
}

// A@go = (A@H)@pW + pb  and  A2@go = (A2@H)@pW + pb  (rows of A / A2 sum to 1).
__global__ void __launch_bounds__(256) proj_aux(const float* __restrict__ pW,
                                                const float* __restrict__ pb) {
    const int row = blockIdx.x * 8 + (threadIdx.x >> 5);
    const int lane = threadIdx.x & 31;
    const int src = (blockIdx.y == 0) ? OFF_AH : OFF_A2H;
    const int dst = (blockIdx.y == 0) ? OFF_AGO : OFF_A2GO;
    float s = g_scratch[src + row * 64 + lane] * pW[lane] +
              g_scratch[src + row * 64 + 32 + lane] * pW[32 + lane];
#pragma unroll
    for (int o = 16; o > 0; o >>= 1) s += __shfl_xor_sync(0xffffffffu, s, o);
    if (lane == 0) g_scratch[dst + row] = s + pb[0];
}

// ---------------------------------------------------------------------------
// Orchestration
// ---------------------------------------------------------------------------
extern "C" void kernel_launch(void* const* d_in, const int* in_sizes, int n_in,
                              void* d_out, int out_size) {
    (void)in_sizes; (void)n_in; (void)out_size;
    const float* x   = (const float*)d_in[0];
    const float* y   = (const float*)d_in[1];
    const float* emb = (const float*)d_in[2];
    const float* egW = (const float*)d_in[3];
    const float* egb = (const float*)d_in[4];
    const float* euW = (const float*)d_in[5];
    const float* eub = (const float*)d_in[6];
    const float* dgW = (const float*)d_in[7];
    const float* dgb = (const float*)d_in[8];
    const float* duW = (const float*)d_in[9];
    const float* dub = (const float*)d_in[10];
    const float* pW  = (const float*)d_in[11];
    const float* pb  = (const float*)d_in[12];
    float* out = (float*)d_out;

    build_A<<<1024, 256>>>(emb);
    make_XY<<<3072, 256>>>(x, y);
    zero_state<<<16384, 256>>>();

    const dim3 gX(6, 8);    // [1024,768] outputs
    const dim3 gH(32, 8);   // [1024,4096] outputs

    // Precompute support-propagated exogenous inputs for all timesteps.
    sgemm128<<<gX, 256>>>(OFF_A, OFF_X,  -1,     OFF_AX,  768, 1024, 0);
    sgemm128<<<gX, 256>>>(OFF_A, OFF_AX, OFF_X,  OFF_A2X, 768, 1024, 1);
    sgemm128<<<gX, 256>>>(OFF_A, OFF_Y,  -1,     OFF_AY,  768, 1024, 0);
    sgemm128<<<gX, 256>>>(OFF_A, OFF_AY, OFF_Y,  OFF_A2Y, 768, 1024, 1);

    // ---------------- Encoder ----------------
    for (int t = 0; t < T_; t++) {
        sgemm128<<<gH, 256>>>(OFF_A, OFF_H,  -1,    OFF_AH,  4096, 1024, 0);
        sgemm128<<<gH, 256>>>(OFF_A, OFF_AH, OFF_H, OFF_A2H, 4096, 1024, 1);
        gcn_gate<1><<<512, 256>>>(OFF_H, OFF_AH, OFF_A2H,
                                  OFF_X, OFF_AX, OFF_A2X,
                                  0, 0, 0, 768, t * 64, 0, 0,
                                  egW, egb, OFF_H, OFF_ZH, OFF_R);
        sgemm128<<<gH, 256>>>(OFF_A, OFF_ZH,  -1,     OFF_AZH,  4096, 1024, 0);
        sgemm128<<<gH, 256>>>(OFF_A, OFF_AZH, OFF_ZH, OFF_A2ZH, 4096, 1024, 1);
        gcn_upd<1><<<512, 256>>>(OFF_ZH, OFF_AZH, OFF_A2ZH,
                                 OFF_X, OFF_AX, OFF_A2X,
                                 0, 0, 0, 768, t * 64, 0, 0,
                                 euW, eub, OFF_H, OFF_R);
    }

    // ---------------- Decoder ----------------
    for (int t = 0; t < HOR_; t++) {
        sgemm128<<<gH, 256>>>(OFF_A, OFF_H,  -1,    OFF_AH,  4096, 1024, 0);
        sgemm128<<<gH, 256>>>(OFF_A, OFF_AH, OFF_H, OFF_A2H, 4096, 1024, 1);
        if (t > 0) {
            // A@go and A2@go via linearity of the projection (A rows sum to 1).
            proj_aux<<<dim3(8192, 2), 256>>>(pW, pb);
        }
        gcn_gate<2><<<512, 256>>>(OFF_H, OFF_AH, OFF_A2H,
                                  OFF_GO, OFF_AGO, OFF_A2GO,
                                  OFF_Y, OFF_AY, OFF_A2Y,
                                  64, 0, 768, t * 64,
                                  dgW, dgb, OFF_H, OFF_ZH, OFF_R);
        sgemm128<<<gH, 256>>>(OFF_A, OFF_ZH,  -1,     OFF_AZH,  4096, 1024, 0);
        sgemm128<<<gH, 256>>>(OFF_A, OFF_AZH, OFF_ZH, OFF_A2ZH, 4096, 1024, 1);
        gcn_upd<2><<<512, 256>>>(OFF_ZH, OFF_AZH, OFF_A2ZH,
                                 OFF_GO, OFF_AGO, OFF_A2GO,
                                 OFF_Y, OFF_AY, OFF_A2Y,
                                 64, 0, 768, t * 64,
                                 duW, dub, OFF_H, OFF_R);
        proj_kernel<<<8192, 256>>>(pW, pb, t, out);
    }
}

// round 3
// speedup vs baseline: 1.5197x; 1.5197x over previous
#include <cuda_runtime.h>

// ---------------------------------------------------------------------------
// Problem constants
// ---------------------------------------------------------------------------
#define B_    64
#define T_    12
#define HOR_  12
#define NN_   1024
#define HH_   64

// Scratch layout (offsets in floats inside one big __device__ buffer)
constexpr int OFF_A    = 0;                         // [1024,1024] tf32-hi
constexpr int OFF_ALO  = OFF_A    + 1024 * 1024;    // [1024,1024] residual
constexpr int OFF_X    = OFF_ALO  + 1024 * 1024;    // [1024, 768]  (n, t*64+b)
constexpr int OFF_AX   = OFF_X    + 1024 * 768;
constexpr int OFF_A2X  = OFF_AX   + 1024 * 768;
constexpr int OFF_Y    = OFF_A2X  + 1024 * 768;
constexpr int OFF_AY   = OFF_Y    + 1024 * 768;
constexpr int OFF_A2Y  = OFF_AY   + 1024 * 768;
constexpr int OFF_H    = OFF_A2Y  + 1024 * 768;     // [1024, 4096] == [65536,64]
constexpr int OFF_AH   = OFF_H    + 4194304;
constexpr int OFF_A2H  = OFF_AH   + 4194304;
constexpr int OFF_ZH   = OFF_A2H  + 4194304;
constexpr int OFF_AZH  = OFF_ZH   + 4194304;
constexpr int OFF_A2ZH = OFF_AZH  + 4194304;
constexpr int OFF_R    = OFF_A2ZH + 4194304;
constexpr int OFF_GO   = OFF_R    + 4194304;        // [65536]
constexpr int OFF_AGO  = OFF_GO   + 65536;
constexpr int OFF_A2GO = OFF_AGO  + 65536;
constexpr int SCRATCH_TOTAL = OFF_A2GO + 65536;     // ~145 MB

__device__ float g_scratch[SCRATCH_TOTAL];

__device__ __forceinline__ unsigned f2tf(float x) {
    unsigned u;
    asm("cvt.rna.tf32.f32 %0, %1;" : "=r"(u) : "f"(x));
    return u;
}

// ---------------------------------------------------------------------------
// A = softmax(relu(E @ E^T), axis=-1),  E: [1024, 8]
// Writes A split into tf32-RN hi part + fp32 residual.
// ---------------------------------------------------------------------------
__global__ void __launch_bounds__(256) build_A(const float* __restrict__ emb) {
    __shared__ float Es[1024 * 8];
    __shared__ float red[256];
    const int tid = threadIdx.x;
    for (int i = tid; i < 1024 * 8; i += 256) Es[i] = emb[i];
    __syncthreads();

    const int r = blockIdx.x;
    float er[8];
#pragma unroll
    for (int j = 0; j < 8; j++) er[j] = Es[r * 8 + j];

    float v[4];
    float mx = -1e30f;
#pragma unroll
    for (int i = 0; i < 4; i++) {
        const int c = tid + i * 256;
        float s = 0.f;
#pragma unroll
        for (int j = 0; j < 8; j++) s += er[j] * Es[c * 8 + j];
        s = fmaxf(s, 0.f);
        v[i] = s;
        mx = fmaxf(mx, s);
    }
    red[tid] = mx;
    __syncthreads();
    for (int o = 128; o > 0; o >>= 1) {
        if (tid < o) red[tid] = fmaxf(red[tid], red[tid + o]);
        __syncthreads();
    }
    mx = red[0];
    __syncthreads();

    float sum = 0.f;
#pragma unroll
    for (int i = 0; i < 4; i++) {
        v[i] = expf(v[i] - mx);
        sum += v[i];
    }
    red[tid] = sum;
    __syncthreads();
    for (int o = 128; o > 0; o >>= 1) {
        if (tid < o) red[tid] += red[tid + o];
        __syncthreads();
    }
    const float inv = 1.f / red[0];
#pragma unroll
    for (int i = 0; i < 4; i++) {
        const float a = v[i] * inv;
        const float ah = __uint_as_float(f2tf(a));
        g_scratch[OFF_A + r * 1024 + tid + i * 256] = ah;
        g_scratch[OFF_ALO + r * 1024 + tid + i * 256] = a - ah;
    }
}

// ---------------------------------------------------------------------------
// Node-major transposes of x and y_cov
// ---------------------------------------------------------------------------
__global__ void __launch_bounds__(256) make_XY(const float* __restrict__ x,
                                               const float* __restrict__ y) {
    const int idx = blockIdx.x * 256 + threadIdx.x;   // 1024*768
    if (idx >= 1024 * 768) return;
    const int n = idx / 768, col = idx % 768;
    const int t = col >> 6, b = col & 63;
    g_scratch[OFF_X + idx] = x[(b * T_ + t) * NN_ + n];
    g_scratch[OFF_Y + idx] = y[(b * HOR_ + t) * NN_ + n];
}

__global__ void __launch_bounds__(256) zero_state() {
    const int i = blockIdx.x * 256 + threadIdx.x;
    if (i < 4194304) g_scratch[OFF_H + i] = 0.f;
    if (i < 65536) {
        g_scratch[OFF_GO + i]   = 0.f;
        g_scratch[OFF_AGO + i]  = 0.f;
        g_scratch[OFF_A2GO + i] = 0.f;
    }
}

// ---------------------------------------------------------------------------
// 2xTF32 tensor-core support GEMM with A hi/lo split + RN-rounded B:
//   C[1024,Nn] = A[1024,1024] @ B[1024,Nn]
//   mode 0: C = A@B          mode 1: C = 2*A@B - D   (Chebyshev)
// 128x128x16 block tiles, 256 thr (8 warps 2x4), 64x32 warp tiles of
// mma.sync.m16n8k8.tf32, cp.async double-buffered.
// ---------------------------------------------------------------------------
#define KDIM 1024
#define NKIT 64

__device__ __forceinline__ void cp16(void* dst_smem, const void* src) {
    unsigned s = (unsigned)__cvta_generic_to_shared(dst_smem);
    asm volatile("cp.async.cg.shared.global [%0], [%1], 16;\n" ::"r"(s), "l"(src));
}
__device__ __forceinline__ void cp_commit() {
    asm volatile("cp.async.commit_group;\n" ::);
}
template <int Nwait>
__device__ __forceinline__ void cp_wait() {
    asm volatile("cp.async.wait_group %0;\n" ::"n"(Nwait));
}
__device__ __forceinline__ void mma_tf32(float* c, const unsigned* a,
                                         const unsigned* b) {
    asm volatile(
        "mma.sync.aligned.m16n8k8.row.col.f32.tf32.tf32.f32 "
        "{%0,%1,%2,%3}, {%4,%5,%6,%7}, {%8,%9}, {%0,%1,%2,%3};\n"
        : "+f"(c[0]), "+f"(c[1]), "+f"(c[2]), "+f"(c[3])
        : "r"(a[0]), "r"(a[1]), "r"(a[2]), "r"(a[3]), "r"(b[0]), "r"(b[1]));
}

__global__ void __launch_bounds__(256) tf32_supp(int offB, int offD,
                                                 int offC, int Nn, int mode) {
    __shared__ float Ah[2][128][20];   // A hi  [m][k]
    __shared__ float Al[2][128][20];   // A lo  [m][k]
    __shared__ float Bs[2][16][136];   // B     [k][n]

    const int tid = threadIdx.x;
    const int lane = tid & 31, wid = tid >> 5;
    const int wm = wid & 1, wn = wid >> 1;          // 2 x 4 warp grid
    const int row0 = blockIdx.y * 128, col0 = blockIdx.x * 128;

    const float* Ahg = g_scratch + OFF_A;
    const float* Alg = g_scratch + OFF_ALO;
    const float* Bg = g_scratch + offB;

    const int ar = tid >> 2;                 // 0..63 (+64 second chunk)
    const int ac = (tid & 3) << 2;           // 0,4,8,12
    const int bk = tid >> 5;                 // 0..7  (+8 second chunk)
    const int bn = (tid & 31) << 2;          // 0..124

    float acc[4][4][4];
#pragma unroll
    for (int i = 0; i < 4; i++)
#pragma unroll
        for (int j = 0; j < 4; j++)
#pragma unroll
            for (int q = 0; q < 4; q++) acc[i][j][q] = 0.f;

    // prologue: tile 0
    {
        const long aoff = (long)(row0 + ar) * KDIM + ac;
        cp16(&Ah[0][ar][ac], Ahg + aoff);
        cp16(&Ah[0][ar + 64][ac], Ahg + aoff + 64 * KDIM);
        cp16(&Al[0][ar][ac], Alg + aoff);
        cp16(&Al[0][ar + 64][ac], Alg + aoff + 64 * KDIM);
        const float* Bp = Bg + bk * Nn + col0 + bn;
        cp16(&Bs[0][bk][bn], Bp);
        cp16(&Bs[0][bk + 8][bn], Bp + 8 * Nn);
        cp_commit();
    }

    for (int k0 = 0; k0 < NKIT; k0++) {
        const int cur = k0 & 1;
        if (k0 + 1 < NKIT) {
            const int nxt = cur ^ 1;
            const int kg = (k0 + 1) << 4;
            const long aoff = (long)(row0 + ar) * KDIM + kg + ac;
            cp16(&Ah[nxt][ar][ac], Ahg + aoff);
            cp16(&Ah[nxt][ar + 64][ac], Ahg + aoff + 64 * KDIM);
            cp16(&Al[nxt][ar][ac], Alg + aoff);
            cp16(&Al[nxt][ar + 64][ac], Alg + aoff + 64 * KDIM);
            const float* Bp = Bg + (kg + bk) * Nn + col0 + bn;
            cp16(&Bs[nxt][bk][bn], Bp);
            cp16(&Bs[nxt][bk + 8][bn], Bp + 8 * Nn);
            cp_commit();
            cp_wait<1>();
        } else {
            cp_wait<0>();
        }
        __syncthreads();

#pragma unroll
        for (int ks = 0; ks < 2; ks++) {
            const int ka = ks * 8 + (lane & 3);
            unsigned ah[4][4], al[4][4], b[4][2];
#pragma unroll
            for (int mt = 0; mt < 4; mt++) {
                const int r = wm * 64 + mt * 16 + (lane >> 2);
                ah[mt][0] = __float_as_uint(Ah[cur][r][ka]);
                ah[mt][1] = __float_as_uint(Ah[cur][r + 8][ka]);
                ah[mt][2] = __float_as_uint(Ah[cur][r][ka + 4]);
                ah[mt][3] = __float_as_uint(Ah[cur][r + 8][ka + 4]);
                al[mt][0] = __float_as_uint(Al[cur][r][ka]);
                al[mt][1] = __float_as_uint(Al[cur][r + 8][ka]);
                al[mt][2] = __float_as_uint(Al[cur][r][ka + 4]);
                al[mt][3] = __float_as_uint(Al[cur][r + 8][ka + 4]);
            }
#pragma unroll
            for (int nt = 0; nt < 4; nt++) {
                const int c = wn * 32 + nt * 8 + (lane >> 2);
                b[nt][0] = f2tf(Bs[cur][ka][c]);
                b[nt][1] = f2tf(Bs[cur][ka + 4][c]);
            }
#pragma unroll
            for (int mt = 0; mt < 4; mt++)
#pragma unroll
                for (int nt = 0; nt < 4; nt++) {
                    mma_tf32(acc[mt][nt], ah[mt], b[nt]);
                    mma_tf32(acc[mt][nt], al[mt], b[nt]);
                }
        }
        __syncthreads();
    }

    // epilogue
    float* Cm = g_scratch + offC;
    const float* Dm = g_scratch + offD;
#pragma unroll
    for (int mt = 0; mt < 4; mt++) {
        const int r = row0 + wm * 64 + mt * 16 + (lane >> 2);
#pragma unroll
        for (int nt = 0; nt < 4; nt++) {
            const int c = col0 + wn * 32 + nt * 8 + ((lane & 3) << 1);
            float2 v0 = make_float2(acc[mt][nt][0], acc[mt][nt][1]);
            float2 v1 = make_float2(acc[mt][nt][2], acc[mt][nt][3]);
            if (mode == 1) {
                const float2 d0 = *(const float2*)(Dm + r * Nn + c);
                const float2 d1 = *(const float2*)(Dm + (r + 8) * Nn + c);
                v0.x = 2.f * v0.x - d0.x; v0.y = 2.f * v0.y - d0.y;
                v1.x = 2.f * v1.x - d1.x; v1.y = 2.f * v1.y - d1.y;
            }
            *(float2*)(Cm + r * Nn + c) = v0;
            *(float2*)(Cm + (r + 8) * Nn + c) = v1;
        }
    }
}

// ---------------------------------------------------------------------------
// Feature gather shared by the fused GCN GEMMs.
// ---------------------------------------------------------------------------
template <int NXC>
__device__ __forceinline__ float gcn_feat(
    int m, int kk, const float* h0, const float* h1, const float* h2,
    const float* x0, const float* x1, const float* x2,
    const float* y0, const float* y1, const float* y2,
    int str0, int off0, int str1, int off1) {
    constexpr int CPK = NXC + 64;
    const int kseg = (kk >= 2 * CPK) ? 2 : ((kk >= CPK) ? 1 : 0);
    const int c = kk - kseg * CPK;
    if (c >= NXC) {
        const float* h = (kseg == 0) ? h0 : ((kseg == 1) ? h1 : h2);
        return h[m * 64 + (c - NXC)];
    } else if (NXC == 2 && c == 1) {
        const float* p = (kseg == 0) ? y0 : ((kseg == 1) ? y1 : y2);
        return p[(m >> 6) * str1 + off1 + (m & 63)];
    } else {
        const float* p = (kseg == 0) ? x0 : ((kseg == 1) ? x1 : x2);
        return p[(m >> 6) * str0 + off0 + (m & 63)];
    }
}

// ---------------------------------------------------------------------------
// Fused gate GCN:  ZR = sigmoid(F @ W + b) -> ZH = z*H, R = r.  NOUT=128
// ---------------------------------------------------------------------------
template <int NXC>
__global__ void __launch_bounds__(256) gcn_gate(
    int oh0, int oh1, int oh2, int ox0, int ox1, int ox2,
    int oy0, int oy1, int oy2, int str0, int off0, int str1, int off1,
    const float* __restrict__ W, const float* __restrict__ bias,
    int oHold, int oZH, int oR) {
    constexpr int CPK = NXC + 64;
    constexpr int KTOT = 3 * CPK;
    __shared__ float As[16][128];
    __shared__ float Bs[16][128];

    const float* h0 = g_scratch + oh0;
    const float* h1 = g_scratch + oh1;
    const float* h2 = g_scratch + oh2;
    const float* x0 = g_scratch + ox0;
    const float* x1 = g_scratch + ox1;
    const float* x2 = g_scratch + ox2;
    const float* y0 = g_scratch + oy0;
    const float* y1 = g_scratch + oy1;
    const float* y2 = g_scratch + oy2;

    const int tid = threadIdx.x;
    const int row0 = blockIdx.x * 128;
    const int tx = tid & 15, ty = tid >> 4;
    const int am = tid >> 1;
    const int ak0 = (tid & 1) * 8;

    float acc[8][8];
#pragma unroll
    for (int i = 0; i < 8; i++)
#pragma unroll
        for (int j = 0; j < 8; j++) acc[i][j] = 0.f;

    for (int k0 = 0; k0 < KTOT; k0 += 16) {
        float av[8], wv[8];
#pragma unroll
        for (int i = 0; i < 8; i++) {
            const int kk = k0 + ak0 + i;
            av[i] = (kk < KTOT)
                        ? gcn_feat<NXC>(row0 + am, kk, h0, h1, h2, x0, x1, x2,
                                        y0, y1, y2, str0, off0, str1, off1)
                        : 0.f;
        }
#pragma unroll
        for (int i = 0; i < 8; i++) {
            const int kl = (tid >> 7) + i * 2;
            const int kk = k0 + kl;
            wv[i] = (kk < KTOT) ? W[kk * 128 + (tid & 127)] : 0.f;
        }
        __syncthreads();
#pragma unroll
        for (int i = 0; i < 8; i++) As[ak0 + i][am] = av[i];
#pragma unroll
        for (int i = 0; i < 8; i++) Bs[(tid >> 7) + i * 2][tid & 127] = wv[i];
        __syncthreads();
#pragma unroll
        for (int k = 0; k < 16; k++) {
            const float4 xa = *(const float4*)&As[k][ty << 2];
            const float4 xb = *(const float4*)&As[k][64 + (ty << 2)];
            const float4 ya = *(const float4*)&Bs[k][tx << 2];
            const float4 yb = *(const float4*)&Bs[k][64 + (tx << 2)];
            const float ra[8] = {xa.x, xa.y, xa.z, xa.w, xb.x, xb.y, xb.z, xb.w};
            const float rb[8] = {ya.x, ya.y, ya.z, ya.w, yb.x, yb.y, yb.z, yb.w};
#pragma unroll
            for (int i = 0; i < 8; i++)
#pragma unroll
                for (int j = 0; j < 8; j++)
                    acc[i][j] = fmaf(ra[i], rb[j], acc[i][j]);
        }
    }

    const float* Hold = g_scratch + oHold;
    float* ZH = g_scratch + oZH;
    float* Rb = g_scratch + oR;
#pragma unroll
    for (int rr = 0; rr < 2; rr++)
#pragma unroll
        for (int ii = 0; ii < 4; ii++) {
            const int m = row0 + rr * 64 + (ty << 2) + ii;
            const int ai = rr * 4 + ii;
#pragma unroll
            for (int j = 0; j < 4; j++) {
                const int c = (tx << 2) + j;
                const float zv = 1.f / (1.f + expf(-(acc[ai][j] + bias[c])));
                ZH[m * 64 + c] = zv * Hold[m * 64 + c];
                const float rv = 1.f / (1.f + expf(-(acc[ai][4 + j] + bias[64 + c])));
                Rb[m * 64 + c] = rv;
            }
        }
}

// ---------------------------------------------------------------------------
// Fused update GCN: hc = tanh(F @ W + b), H = r*H + (1-r)*hc.  NOUT = 64.
// ---------------------------------------------------------------------------
template <int NXC>
__global__ void __launch_bounds__(256) gcn_upd(
    int oh0, int oh1, int oh2, int ox0, int ox1, int ox2,
    int oy0, int oy1, int oy2, int str0, int off0, int str1, int off1,
    const float* __restrict__ W, const float* __restrict__ bias,
    int oH, int oR) {
    constexpr int CPK = NXC + 64;
    constexpr int KTOT = 3 * CPK;
    __shared__ float As[16][128];
    __shared__ float Bs[16][64];

    const float* h0 = g_scratch + oh0;
    const float* h1 = g_scratch + oh1;
    const float* h2 = g_scratch + oh2;
    const float* x0 = g_scratch + ox0;
    const float* x1 = g_scratch + ox1;
    const float* x2 = g_scratch + ox2;
    const float* y0 = g_scratch + oy0;
    const float* y1 = g_scratch + oy1;
    const float* y2 = g_scratch + oy2;

    const int tid = threadIdx.x;
    const int row0 = blockIdx.x * 128;
    const int tx = tid & 15, ty = tid >> 4;
    const int am = tid >> 1;
    const int ak0 = (tid & 1) * 8;

    float acc[8][4];
#pragma unroll
    for (int i = 0; i < 8; i++)
#pragma unroll
        for (int j = 0; j < 4; j++) acc[i][j] = 0.f;

    for (int k0 = 0; k0 < KTOT; k0 += 16) {
        float av[8], wv[4];
#pragma unroll
        for (int i = 0; i < 8; i++) {
            const int kk = k0 + ak0 + i;
            av[i] = (kk < KTOT)
                        ? gcn_feat<NXC>(row0 + am, kk, h0, h1, h2, x0, x1, x2,
                                        y0, y1, y2, str0, off0, str1, off1)
                        : 0.f;
        }
#pragma unroll
        for (int i = 0; i < 4; i++) {
            const int kl = (tid >> 6) + (i << 2);
            const int kk = k0 + kl;
            wv[i] = (kk < KTOT) ? W[kk * 64 + (tid & 63)] : 0.f;
        }
        __syncthreads();
#pragma unroll
        for (int i = 0; i < 8; i++) As[ak0 + i][am] = av[i];
#pragma unroll
        for (int i = 0; i < 4; i++) Bs[(tid >> 6) + (i << 2)][tid & 63] = wv[i];
        __syncthreads();
#pragma unroll
        for (int k = 0; k < 16; k++) {
            const float4 xa = *(const float4*)&As[k][ty << 2];
            const float4 xb = *(const float4*)&As[k][64 + (ty << 2)];
            const float4 yy = *(const float4*)&Bs[k][tx << 2];
            const float ra[8] = {xa.x, xa.y, xa.z, xa.w, xb.x, xb.y, xb.z, xb.w};
            const float rb[4] = {yy.x, yy.y, yy.z, yy.w};
#pragma unroll
            for (int i = 0; i < 8; i++)
#pragma unroll
                for (int j = 0; j < 4; j++)
                    acc[i][j] = fmaf(ra[i], rb[j], acc[i][j]);
        }
    }

    float* H = g_scratch + oH;
    const float* Rb = g_scratch + oR;
#pragma unroll
    for (int rr = 0; rr < 2; rr++)
#pragma unroll
        for (int ii = 0; ii < 4; ii++) {
            const int m = row0 + rr * 64 + (ty << 2) + ii;
            const int ai = rr * 4 + ii;
#pragma unroll
            for (int j = 0; j < 4; j++) {
                const int c = (tx << 2) + j;
                const float hc = tanhf(acc[ai][j] + bias[c]);
                const float rv = Rb[m * 64 + c];
                const float ho = H[m * 64 + c];
                H[m * 64 + c] = rv * ho + (1.f - rv) * hc;
            }
        }
}

// ---------------------------------------------------------------------------
// Decoder projection kernels
// ---------------------------------------------------------------------------
__global__ void __launch_bounds__(256) proj_kernel(const float* __restrict__ pW,
                                                   const float* __restrict__ pb,
                                                   int t, float* __restrict__ out) {
    const int row = blockIdx.x * 8 + (threadIdx.x >> 5);
    const int lane = threadIdx.x & 31;
    const float* Hp = g_scratch + OFF_H;
    float s = Hp[row * 64 + lane] * pW[lane] + Hp[row * 64 + 32 + lane] * pW[32 + lane];
#pragma unroll
    for (int o = 16; o > 0; o >>= 1) s += __shfl_xor_sync(0xffffffffu, s, o);
    if (lane == 0) {
        const float go = s + pb[0];
        g_scratch[OFF_GO + row] = go;
        const int n = row >> 6, b = row & 63;
        out[(b * HOR_ + t) * NN_ + n] = go;
    }
}

__global__ void __launch_bounds__(256) proj_aux(const float* __restrict__ pW,
                                                const float* __restrict__ pb) {
    const int row = blockIdx.x * 8 + (threadIdx.x >> 5);
    const int lane = threadIdx.x & 31;
    const int src = (blockIdx.y == 0) ? OFF_AH : OFF_A2H;
    const int dst = (blockIdx.y == 0) ? OFF_AGO : OFF_A2GO;
    float s = g_scratch[src + row * 64 + lane] * pW[lane] +
              g_scratch[src + row * 64 + 32 + lane] * pW[32 + lane];
#pragma unroll
    for (int o = 16; o > 0; o >>= 1) s += __shfl_xor_sync(0xffffffffu, s, o);
    if (lane == 0) g_scratch[dst + row] = s + pb[0];
}

// ---------------------------------------------------------------------------
// Orchestration
// ---------------------------------------------------------------------------
extern "C" void kernel_launch(void* const* d_in, const int* in_sizes, int n_in,
                              void* d_out, int out_size) {
    (void)in_sizes; (void)n_in; (void)out_size;
    const float* x   = (const float*)d_in[0];
    const float* y   = (const float*)d_in[1];
    const float* emb = (const float*)d_in[2];
    const float* egW = (const float*)d_in[3];
    const float* egb = (const float*)d_in[4];
    const float* euW = (const float*)d_in[5];
    const float* eub = (const float*)d_in[6];
    const float* dgW = (const float*)d_in[7];
    const float* dgb = (const float*)d_in[8];
    const float* duW = (const float*)d_in[9];
    const float* dub = (const float*)d_in[10];
    const float* pW  = (const float*)d_in[11];
    const float* pb  = (const float*)d_in[12];
    float* out = (float*)d_out;

    build_A<<<1024, 256>>>(emb);
    make_XY<<<3072, 256>>>(x, y);
    zero_state<<<16384, 256>>>();

    const dim3 gX(6, 8);    // [1024,768] outputs
    const dim3 gH(32, 8);   // [1024,4096] outputs

    // Precompute support-propagated exogenous inputs for all timesteps.
    tf32_supp<<<gX, 256>>>(OFF_X,  0,      OFF_AX,  768, 0);
    tf32_supp<<<gX, 256>>>(OFF_AX, OFF_X,  OFF_A2X, 768, 1);
    tf32_supp<<<gX, 256>>>(OFF_Y,  0,      OFF_AY,  768, 0);
    tf32_supp<<<gX, 256>>>(OFF_AY, OFF_Y,  OFF_A2Y, 768, 1);

    // ---------------- Encoder ----------------
    for (int t = 0; t < T_; t++) {
        tf32_supp<<<gH, 256>>>(OFF_H,  0,     OFF_AH,  4096, 0);
        tf32_supp<<<gH, 256>>>(OFF_AH, OFF_H, OFF_A2H, 4096, 1);
        gcn_gate<1><<<512, 256>>>(OFF_H, OFF_AH, OFF_A2H,
                                  OFF_X, OFF_AX, OFF_A2X,
                                  0, 0, 0, 768, t * 64, 0, 0,
                                  egW, egb, OFF_H, OFF_ZH, OFF_R);
        tf32_supp<<<gH, 256>>>(OFF_ZH,  0,      OFF_AZH,  4096, 0);
        tf32_supp<<<gH, 256>>>(OFF_AZH, OFF_ZH, OFF_A2ZH, 4096, 1);
        gcn_upd<1><<<512, 256>>>(OFF_ZH, OFF_AZH, OFF_A2ZH,
                                 OFF_X, OFF_AX, OFF_A2X,
                                 0, 0, 0, 768, t * 64, 0, 0,
                                 euW, eub, OFF_H, OFF_R);
    }

    // ---------------- Decoder ----------------
    for (int t = 0; t < HOR_; t++) {
        tf32_supp<<<gH, 256>>>(OFF_H,  0,     OFF_AH,  4096, 0);
        tf32_supp<<<gH, 256>>>(OFF_AH, OFF_H, OFF_A2H, 4096, 1);
        if (t > 0) {
            proj_aux<<<dim3(8192, 2), 256>>>(pW, pb);
        }
        gcn_gate<2><<<512, 256>>>(OFF_H, OFF_AH, OFF_A2H,
                                  OFF_GO, OFF_AGO, OFF_A2GO,
                                  OFF_Y, OFF_AY, OFF_A2Y,
                                  64, 0, 768, t * 64,
                                  dgW, dgb, OFF_H, OFF_ZH, OFF_R);
        tf32_supp<<<gH, 256>>>(OFF_ZH,  0,      OFF_AZH,  4096, 0);
        tf32_supp<<<gH, 256>>>(OFF_AZH, OFF_ZH, OFF_A2ZH, 4096, 1);
        gcn_upd<2><<<512, 256>>>(OFF_ZH, OFF_AZH, OFF_A2ZH,
                                 OFF_GO, OFF_AGO, OFF_A2GO,
                                 OFF_Y, OFF_AY, OFF_A2Y,
                                 64, 0, 768, t * 64,
                                 duW, dub, OFF_H, OFF_R);
        proj_kernel<<<8192, 256>>>(pW, pb, t, out);
    }
}